// round 12
// baseline (speedup 1.0000x reference)
#include <cuda_runtime.h>
#include <cuda_bf16.h>
#include <cstdint>

#define DIM 4096
#define THREADS 256

// In-register 16-point Walsh-Hadamard (unnormalized butterflies).
__device__ __forceinline__ void fwht16(float r[16]) {
#pragma unroll
    for (int h = 1; h < 16; h <<= 1) {
#pragma unroll
        for (int k = 0; k < 16; k++) {
            if ((k & h) == 0) {
                float a = r[k];
                float b = r[k + h];
                r[k]     = a + b;
                r[k + h] = a - b;
            }
        }
    }
}

__global__ __launch_bounds__(THREADS, 8)   // target: 8 CTAs/SM = 64 warps (reg cap 32)
void fwht4096_kernel(const float* __restrict__ x, float* __restrict__ y) {
    // Layout 1 (exchange 1): element i at phys1 = (i>>5)*36 + (i&31).
    // Layout 2 (exchange 2): value (u', c') at phys2 = u'*17 + c'.
    __shared__ float s[4608];   // 18432 B (max phys1 = 4603, max phys2 = 4350)

    const int t    = threadIdx.x;
    const int w    = t >> 5;    // 0..7
    const int lane = t & 31;

    const float* xr = x + (size_t)blockIdx.x * DIM;
    float*       yr = y + (size_t)blockIdx.x * DIM;

    float r[16];

    // ---- Load: r[j] = x[lane + 32w + 256j]. Fixed j: warp covers one
    // contiguous 128B line (sector-perfect). j == i bits 8..11.
    {
        const float* xp = xr + (w << 5) + lane;
#pragma unroll
        for (int j = 0; j < 16; j++)
            r[j] = xp[j << 8];
    }

    // ---- Phase A: butterflies over i bits 8..11.
    fwht16(r);

    // ---- Exchange 1 write: i = lane + 32w + 256j -> phys1 = (w + 8j)*36 + lane.
    // Banks (36w + 288j + lane) mod 32 = (4w + lane): distinct per lane. CF.
    {
        float* sp = &s[w * 36 + lane];
#pragma unroll
        for (int j = 0; j < 16; j++)
            sp[j * 288] = r[j];
    }
    __syncthreads();

    // ---- Exchange 1 read: thread u owns i = 16u + c, c = 0..15.
    // phys1 = (u>>1)*36 + (u&1)*16 + c: contiguous, 16B-aligned -> 4x LDS.128.
    // Banks 4(l>>1) + 16(l&1) + 4m: disjoint per quarter-warp. CF.
    {
        const float4* s4 = reinterpret_cast<const float4*>(
            &s[(t >> 1) * 36 + (t & 1) * 16]);
#pragma unroll
        for (int m = 0; m < 4; m++) {
            float4 v = s4[m];
            r[4*m+0] = v.x; r[4*m+1] = v.y; r[4*m+2] = v.z; r[4*m+3] = v.w;
        }
    }

    // ---- Phase B: butterflies over i bits 0..3.
    fwht16(r);

    // ---- Layout change (phys1 -> phys2): all ex1 reads must finish first.
    __syncthreads();

    // ---- Exchange 2 write: thread u holds (u' = u, c' = 0..15) -> s[u*17 + c].
    // Fixed c: banks (17*lane + c) mod 32, gcd(17,32)=1 -> distinct. CF.
    {
        float* sp = &s[t * 17];
#pragma unroll
        for (int c = 0; c < 16; c++)
            sp[c] = r[c];
    }
    __syncthreads();

    // ---- Exchange 2 read: reg d gets i = llo + 16d + 256h + 512w
    // (llo = lane&15, h = lane>>4). Owner u' = d + 16h + 32w, c' = llo
    // -> phys2 = (d + 16h + 32w)*17 + llo.
    // Banks (17d + 16h + llo) mod 32 = (17d + lane): distinct per lane. CF.
    const int h   = lane >> 4;
    const int llo = lane & 15;
    {
        const float* sp = &s[((h << 4) + (w << 5)) * 17 + llo];
#pragma unroll
        for (int d = 0; d < 16; d++)
            r[d] = sp[d * 17];
    }

    // ---- Phase C: butterflies over i bits 4..7 (== bits of d).
    fwht16(r);

    // ---- Store: i = llo + 16d + 256h + 512w. Fixed d: half-warp pairs of
    // 64B chunks (2 lines/instr). Scale 1/sqrt(4096) = 1/64 (exact).
    const float sc = 0.015625f;
    {
        float* yp = yr + llo + (h << 8) + (w << 9);
#pragma unroll
        for (int d = 0; d < 16; d++)
            yp[d << 4] = r[d] * sc;
    }
}

extern "C" void kernel_launch(void* const* d_in, const int* in_sizes, int n_in,
                              void* d_out, int out_size) {
    const float* x = (const float*)d_in[0];
    float* y = (float*)d_out;
    const int n = in_sizes[0];
    const int rows = n / DIM;   // 8192
    fwht4096_kernel<<<rows, THREADS>>>(x, y);
}

// round 15
// speedup vs baseline: 1.0426x; 1.0426x over previous
#include <cuda_runtime.h>
#include <cuda_fp16.h>
#include <cstdint>

#define DIM 4096
#define THREADS 128
#define SROWH 40   // halfs per 32-elem group (80B rows): 16B-aligned, CF in all 4 patterns

// In-register 32-point Walsh-Hadamard (unnormalized butterflies).
__device__ __forceinline__ void fwht32(float r[32]) {
#pragma unroll
    for (int h = 1; h < 32; h <<= 1) {
#pragma unroll
        for (int k = 0; k < 32; k++) {
            if ((k & h) == 0) {
                float a = r[k];
                float b = r[k + h];
                r[k]     = a + b;
                r[k + h] = a - b;
            }
        }
    }
}

__global__ __launch_bounds__(THREADS, 10)   // proven reg/occ balance (~48 regs)
void fwht4096_kernel(const float* __restrict__ x, float* __restrict__ y) {
    // Element group g = i>>5 lives at half-row [g*40, g*40+32), column i&31.
    __shared__ __align__(16) __half s[128 * SROWH];   // 10240 B

    const int t    = threadIdx.x;
    const int w    = t >> 5;
    const int lane = t & 31;

    const float* xr = x + (size_t)blockIdx.x * DIM;
    float*       yr = y + (size_t)blockIdx.x * DIM;

    float r[32];

    // ---- Load: r[k] = x[k*128 + t]. One contiguous 128B line per warp per k;
    // 32 independent loads -> deep MLP.
#pragma unroll
    for (int k = 0; k < 32; k++)
        r[k] = xr[k * 128 + t];

    // ---- Phase A: butterflies over i bits 7..11 (== bits of k).
    fwht32(r);

    // ---- Exchange 1 write (fp16): i = k*128 + t -> half-idx (4k+w)*40 + lane.
    // Lanes span 16 consecutive 32-bit words (2 lanes merge per word) -> CF,
    // 64B per instruction.
#pragma unroll
    for (int k = 0; k < 32; k++)
        s[(4 * k + w) * SROWH + lane] = __float2half(r[k]);
    __syncthreads();

    // ---- Exchange 1 read: thread t owns i = t*32 + c, c = 0..31.
    // Row base byte 80t (16B-aligned) -> 4x LDS.128 (8 halfs each).
    // Quarter-warp chunk starts 20t mod 32 = {0,4,...,28}: bank-disjoint. CF.
    {
        const uint4* s4 = reinterpret_cast<const uint4*>(&s[t * SROWH]);
#pragma unroll
        for (int m = 0; m < 4; m++) {
            uint4 v = s4[m];
            const uint32_t wd[4] = {v.x, v.y, v.z, v.w};
#pragma unroll
            for (int j = 0; j < 4; j++) {
                float2 f = __half22float2(*reinterpret_cast<const __half2*>(&wd[j]));
                r[8 * m + 2 * j]     = f.x;
                r[8 * m + 2 * j + 1] = f.y;
            }
        }
    }

    // ---- Phase B: butterflies over i bits 0..4 (== bits of c).
    fwht32(r);

    // ---- Exchange 2 write (fp16, packed): back into the SAME row this thread
    // just read -> no barrier needed before this write. 16 half2 -> 4x STS.128.
    {
        uint4* s4 = reinterpret_cast<uint4*>(&s[t * SROWH]);
#pragma unroll
        for (int m = 0; m < 4; m++) {
            uint32_t wd[4];
#pragma unroll
            for (int j = 0; j < 4; j++) {
                __half2 h = __floats2half2_rn(r[8 * m + 2 * j], r[8 * m + 2 * j + 1]);
                wd[j] = *reinterpret_cast<const uint32_t*>(&h);
            }
            uint4 v; v.x = wd[0]; v.y = wd[1]; v.z = wd[2]; v.w = wd[3];
            s4[m] = v;
        }
    }
    __syncthreads();

    // ---- Exchange 2 read: reg d <- i = 32d + 1024w + lane
    // (bits{5..9} = d, bits{10,11} = w, bits{0..4} = lane).
    // half-idx (d + 32w)*40 + lane: lanes span 16 words (pairs merge) -> CF.
#pragma unroll
    for (int d = 0; d < 32; d++)
        r[d] = __half2float(s[(d + 32 * w) * SROWH + lane]);

    // ---- Phase C: butterflies over i bits 5,6 (== d bits 0,1) in registers.
#pragma unroll
    for (int d = 0; d < 32; d += 2) {
        float a = r[d], b = r[d + 1];
        r[d]     = a + b;
        r[d + 1] = a - b;
    }
#pragma unroll
    for (int d = 0; d < 32; d++) {
        if ((d & 2) == 0) {
            float a = r[d], b = r[d + 2];
            r[d]     = a + b;
            r[d + 2] = a - b;
        }
    }

    // ---- Store: i = lane + 32*(d&3) + 128*(d>>2) + 1024w. Fixed d: one
    // contiguous 128B line per warp. Scale 1/sqrt(4096) = 1/64 (exact).
    const float sc = 0.015625f;
    float* yw = yr + (w << 10) + lane;
#pragma unroll
    for (int d = 0; d < 32; d++)
        yw[((d & 3) << 5) + ((d >> 2) << 7)] = r[d] * sc;
}

extern "C" void kernel_launch(void* const* d_in, const int* in_sizes, int n_in,
                              void* d_out, int out_size) {
    const float* x = (const float*)d_in[0];
    float* y = (float*)d_out;
    const int n = in_sizes[0];
    const int rows = n / DIM;   // 8192
    fwht4096_kernel<<<rows, THREADS>>>(x, y);
}